// round 1
// baseline (speedup 1.0000x reference)
#include <cuda_runtime.h>
#include <cuda_bf16.h>
#include <cstdint>

#define NUM_T 64
#define DIN   4096
#define DOUT  11008

// Scratch (allocation-free rule: __device__ globals)
__device__ __align__(256) __nv_bfloat16 g_xq[NUM_T * DIN];
__device__ __align__(256) __nv_bfloat16 g_wq[DOUT * DIN];
__device__ __align__(256) float         g_bq[DOUT];

// ---------------------------------------------------------------------------
// MXFP4 quant-dequant math (matches reference exactly; all pow2 ops are exact)
// ---------------------------------------------------------------------------
__device__ __forceinline__ void mk_scale(float amax, float& scale, float& inv_scale) {
    if (!(amax > 0.0f)) amax = 1.0f;                       // amax==0 (or NaN) -> 1.0
    int e  = ((__float_as_int(amax) >> 23) & 0xFF) - 127;  // floor(log2) for normals
    int se = min(max(e - 2, -127), 127);
    scale = (se >= -126) ? __int_as_float((se + 127) << 23)
                         : 5.877471754111438e-39f;         // 2^-127 (subnormal)
    inv_scale = __int_as_float((127 - se) << 23);          // 2^-se
}

__device__ __forceinline__ float qdq1(float t, float inv_scale, float scale) {
    float v  = t * inv_scale;                 // exact (pow2)
    float a  = fminf(fabsf(v), 6.0f);         // saturate to E2M1 max
    float am = fmaxf(a, 0.0009765625f);       // 2^-10 guard
    int ae = ((__float_as_int(am) >> 23) & 0xFF) - 127;
    ae = min(max(ae, 0), 2);
    float step  = __int_as_float((ae + 126) << 23);   // 2^(ae-1)
    float istep = __int_as_float((128 - ae) << 23);   // 2^(1-ae)
    float q = rintf(a * istep) * step;                // rintf = round half-to-even (jnp.round)
    return copysignf(q * scale, v);
}

// ---------------------------------------------------------------------------
// Vectorized qdq -> bf16. One MXFP block (32 floats) = 8 lanes x float4.
// n must be a multiple of 128 (holds: 262144 and 45088768).
// ---------------------------------------------------------------------------
__global__ void qdq_bf16_kernel(const float* __restrict__ in,
                                __nv_bfloat16* __restrict__ out, int n) {
    int warp = (blockIdx.x * blockDim.x + threadIdx.x) >> 5;
    int lane = threadIdx.x & 31;
    long base = (long)warp * 128 + (long)lane * 4;
    if (base >= n) return;
    float4 v = *reinterpret_cast<const float4*>(in + base);
    float am = fmaxf(fmaxf(fabsf(v.x), fabsf(v.y)), fmaxf(fabsf(v.z), fabsf(v.w)));
    am = fmaxf(am, __shfl_xor_sync(0xffffffffu, am, 1));
    am = fmaxf(am, __shfl_xor_sync(0xffffffffu, am, 2));
    am = fmaxf(am, __shfl_xor_sync(0xffffffffu, am, 4));   // absmax over 8-lane group
    float scale, inv;
    mk_scale(am, scale, inv);
    __nv_bfloat162 r0, r1;
    r0.x = __float2bfloat16(qdq1(v.x, inv, scale));  // exact: <=2 mantissa bits
    r0.y = __float2bfloat16(qdq1(v.y, inv, scale));
    r1.x = __float2bfloat16(qdq1(v.z, inv, scale));
    r1.y = __float2bfloat16(qdq1(v.w, inv, scale));
    uint2 packed;
    packed.x = *reinterpret_cast<uint32_t*>(&r0);
    packed.y = *reinterpret_cast<uint32_t*>(&r1);
    *reinterpret_cast<uint2*>(out + base) = packed;
}

// bias qdq: one warp per 32-block, fp32 out
__global__ void qdq_bias_kernel(const float* __restrict__ in, float* __restrict__ out, int n) {
    int warp = (blockIdx.x * blockDim.x + threadIdx.x) >> 5;
    int lane = threadIdx.x & 31;
    int idx = warp * 32 + lane;
    if (idx >= n) return;
    float t = in[idx];
    float am = fabsf(t);
    #pragma unroll
    for (int o = 1; o < 32; o <<= 1)
        am = fmaxf(am, __shfl_xor_sync(0xffffffffu, am, o));
    float scale, inv;
    mk_scale(am, scale, inv);
    out[idx] = qdq1(t, inv, scale);
}

// ---------------------------------------------------------------------------
// bf16 GEMM: out[64,11008] = xq[64,4096] @ wq[11008,4096]^T + bq
// CTA: 64(M) x 64(N), 256 threads (8 warps in 4x2), K-chunks of 64.
// mma.sync.m16n8k16 row.col f32.bf16.bf16.f32, ldmatrix from padded smem.
// ---------------------------------------------------------------------------
#define KC 64
#define NT 64
#define SSTRIDE 72   // +8 bf16 pad -> conflict-free ldmatrix (row stride 144B)

#define LDMATRIX_X4(r0, r1, r2, r3, addr)                                     \
    asm volatile("ldmatrix.sync.aligned.m8n8.x4.shared.b16 {%0,%1,%2,%3}, [%4];" \
                 : "=r"(r0), "=r"(r1), "=r"(r2), "=r"(r3) : "r"(addr))

#define MMA16816(c, a0, a1, a2, a3, b0, b1)                                   \
    asm volatile("mma.sync.aligned.m16n8k16.row.col.f32.bf16.bf16.f32 "       \
                 "{%0,%1,%2,%3}, {%4,%5,%6,%7}, {%8,%9}, {%0,%1,%2,%3};"      \
                 : "+f"(c[0]), "+f"(c[1]), "+f"(c[2]), "+f"(c[3])             \
                 : "r"(a0), "r"(a1), "r"(a2), "r"(a3), "r"(b0), "r"(b1))

__global__ __launch_bounds__(256) void gemm_kernel(float* __restrict__ out) {
    __shared__ __nv_bfloat16 Xs[NUM_T][SSTRIDE];
    __shared__ __nv_bfloat16 Ws[NT][SSTRIDE];

    int tid  = threadIdx.x;
    int w    = tid >> 5;
    int lane = tid & 31;
    int nbase = blockIdx.x * NT;
    int mrow  = (w >> 1) * 16;   // 0,16,32,48
    int ncol  = (w & 1) * 32;    // 0 or 32

    float acc[4][4];
    #pragma unroll
    for (int i = 0; i < 4; i++)
        #pragma unroll
        for (int j = 0; j < 4; j++) acc[i][j] = 0.0f;

    int q = lane >> 3, li = lane & 7;
    // A fragment ldmatrix addresses: m0..m3 = {r0-7 k0-7, r8-15 k0-7, r0-7 k8-15, r8-15 k8-15}
    uint32_t a_base = (uint32_t)__cvta_generic_to_shared(
        &Xs[mrow + (q & 1) * 8 + li][(q >> 1) * 8]);
    // B fragment: m0..m3 = {n0-7 k0-7, n0-7 k8-15, n8-15 k0-7, n8-15 k8-15}
    uint32_t b_base0 = (uint32_t)__cvta_generic_to_shared(
        &Ws[ncol + (q >> 1) * 8 + li][(q & 1) * 8]);
    uint32_t b_base1 = b_base0 + 16 * SSTRIDE * 2;   // +16 N rows

    for (int kc = 0; kc < DIN; kc += KC) {
        #pragma unroll
        for (int i = 0; i < 2; i++) {
            int c   = tid + i * 256;        // 0..511
            int row = c >> 3;
            int cc  = (c & 7) * 8;
            *reinterpret_cast<float4*>(&Xs[row][cc]) =
                *reinterpret_cast<const float4*>(&g_xq[row * DIN + kc + cc]);
            *reinterpret_cast<float4*>(&Ws[row][cc]) =
                *reinterpret_cast<const float4*>(&g_wq[(size_t)(nbase + row) * DIN + kc + cc]);
        }
        __syncthreads();
        #pragma unroll
        for (int ks = 0; ks < 4; ks++) {
            uint32_t a0, a1, a2, a3;
            LDMATRIX_X4(a0, a1, a2, a3, a_base + ks * 32);
            #pragma unroll
            for (int nb = 0; nb < 2; nb++) {
                uint32_t b0, b1, b2, b3;
                LDMATRIX_X4(b0, b1, b2, b3, (nb ? b_base1 : b_base0) + ks * 32);
                MMA16816(acc[nb * 2 + 0], a0, a1, a2, a3, b0, b1);
                MMA16816(acc[nb * 2 + 1], a0, a1, a2, a3, b2, b3);
            }
        }
        __syncthreads();
    }

    // epilogue: C thread map: rows (t/4, t/4+8), cols 2*(t%4), 2*(t%4)+1
    int tg = lane >> 2, tig = lane & 3;
    #pragma unroll
    for (int nf = 0; nf < 4; nf++) {
        int col = nbase + ncol + nf * 8 + tig * 2;
        int r0  = mrow + tg;
        float bv0 = g_bq[col], bv1 = g_bq[col + 1];
        out[(size_t)r0 * DOUT + col]           = acc[nf][0] + bv0;
        out[(size_t)r0 * DOUT + col + 1]       = acc[nf][1] + bv1;
        out[(size_t)(r0 + 8) * DOUT + col]     = acc[nf][2] + bv0;
        out[(size_t)(r0 + 8) * DOUT + col + 1] = acc[nf][3] + bv1;
    }
}

// ---------------------------------------------------------------------------
extern "C" void kernel_launch(void* const* d_in, const int* in_sizes, int n_in,
                              void* d_out, int out_size) {
    const float* x = nullptr;
    const float* wgt = nullptr;
    const float* bias = nullptr;
    for (int i = 0; i < n_in; i++) {
        if (in_sizes[i] == NUM_T * DIN)       x    = (const float*)d_in[i];
        else if (in_sizes[i] == DOUT * DIN)   wgt  = (const float*)d_in[i];
        else if (in_sizes[i] == DOUT)         bias = (const float*)d_in[i];
    }
    float* out = (float*)d_out;

    void *xq_p = nullptr, *wq_p = nullptr, *bq_p = nullptr;
    cudaGetSymbolAddress(&xq_p, g_xq);
    cudaGetSymbolAddress(&wq_p, g_wq);
    cudaGetSymbolAddress(&bq_p, g_bq);

    {   // x: 262144 elems -> 2048 warps -> 256 blocks of 256
        int nwarps = (NUM_T * DIN) / 128;
        qdq_bf16_kernel<<<(nwarps + 7) / 8, 256>>>(x, (__nv_bfloat16*)xq_p, NUM_T * DIN);
    }
    {   // w: 45088768 elems -> 352256 warps -> 44032 blocks of 256
        int nwarps = (DOUT * DIN) / 128;
        qdq_bf16_kernel<<<(nwarps + 7) / 8, 256>>>(wgt, (__nv_bfloat16*)wq_p, DOUT * DIN);
    }
    {   // bias: 344 warps -> 43 blocks of 256
        qdq_bias_kernel<<<43, 256>>>(bias, (float*)bq_p, DOUT);
    }
    gemm_kernel<<<DOUT / NT, 256>>>(out);
    (void)out_size;
}

// round 3
// speedup vs baseline: 1.7789x; 1.7789x over previous
#include <cuda_runtime.h>
#include <cuda_fp16.h>
#include <cstdint>

#define NUM_T 64
#define DIN   4096
#define DOUT  11008
#define KS    4
#define KPER  (DIN / KS)     // 1024
#define KC    64
#define NT    64
#define SSTRIDE 72           // +8 half pad: row stride 144B (16B-aligned, conflict-free ldmatrix)

// Scratch (allocation-free rule: __device__ globals)
__device__ __align__(256) __half g_xq[NUM_T * DIN];
__device__ __align__(256) float  g_part[KS * NUM_T * DOUT];   // 11.27 MB

// ---------------------------------------------------------------------------
// MXFP scale: scale = 2^clip(floor(log2 amax) - 2, -127, 127)
// ---------------------------------------------------------------------------
__device__ __forceinline__ void mk_scale(float amax, float& scale, float& inv_scale) {
    if (!(amax > 0.0f)) amax = 1.0f;
    int e  = ((__float_as_int(amax) >> 23) & 0xFF) - 127;   // floor(log2) for normals
    int se = min(max(e - 2, -127), 127);
    scale = (se >= -126) ? __int_as_float((se + 127) << 23)
                         : 5.877471754111438e-39f;          // 2^-127 subnormal
    inv_scale = __int_as_float((127 - se) << 23);           // 2^-se (|se|<=127 -> normal)
}

// E2M1 quant-dequant of one scaled value (portable ALU path, matches reference
// exactly: clip to 6, round-half-even on the E2M1 grid incl. 0.5 subnormal step).
__device__ __forceinline__ float qdq1(float t, float inv_scale, float scale) {
    float v  = t * inv_scale;                 // exact (pow2)
    float a  = fminf(fabsf(v), 6.0f);
    float am = fmaxf(a, 0.0009765625f);       // 2^-10 guard
    int ae = ((__float_as_int(am) >> 23) & 0xFF) - 127;
    ae = min(max(ae, 0), 2);
    float step  = __int_as_float((ae + 126) << 23);   // 2^(ae-1)
    float istep = __int_as_float((128 - ae) << 23);   // 2^(1-ae)
    float q = rintf(a * istep) * step;                // rintf = round half-to-even
    return copysignf(q * scale, v);                   // exact: <=2 sig bits * pow2
}

// ---------------------------------------------------------------------------
// x quant-dequant -> f16. One MXFP block (32 floats) = 8 lanes x float4.
// ---------------------------------------------------------------------------
__global__ void qdq_x_kernel(const float* __restrict__ in) {
    int warp = (blockIdx.x * blockDim.x + threadIdx.x) >> 5;
    int lane = threadIdx.x & 31;
    long base = (long)warp * 128 + (long)lane * 4;
    if (base >= NUM_T * DIN) return;
    float4 v = *reinterpret_cast<const float4*>(in + base);
    float am = fmaxf(fmaxf(fabsf(v.x), fabsf(v.y)), fmaxf(fabsf(v.z), fabsf(v.w)));
    am = fmaxf(am, __shfl_xor_sync(0xffffffffu, am, 1));
    am = fmaxf(am, __shfl_xor_sync(0xffffffffu, am, 2));
    am = fmaxf(am, __shfl_xor_sync(0xffffffffu, am, 4));
    float scale, inv;
    mk_scale(am, scale, inv);
    __half2 h0 = __floats2half2_rn(qdq1(v.x, inv, scale), qdq1(v.y, inv, scale));
    __half2 h1 = __floats2half2_rn(qdq1(v.z, inv, scale), qdq1(v.w, inv, scale));
    uint2 st;
    st.x = *reinterpret_cast<uint32_t*>(&h0);
    st.y = *reinterpret_cast<uint32_t*>(&h1);
    *reinterpret_cast<uint2*>(&g_xq[base]) = st;
}

// ---------------------------------------------------------------------------
// Fused GEMM: partial[s] = xq[64,KPER] @ qdq(W[n:n+64, s*KPER:(s+1)*KPER])^T
// CTA 64(M) x 64(N) x KPER(K), 256 thr (8 warps 4x2), W quantized in-register.
// ---------------------------------------------------------------------------
#define LDMATRIX_X4(r0, r1, r2, r3, addr)                                        \
    asm volatile("ldmatrix.sync.aligned.m8n8.x4.shared.b16 {%0,%1,%2,%3}, [%4];" \
                 : "=r"(r0), "=r"(r1), "=r"(r2), "=r"(r3) : "r"(addr))

#define MMA16816(c, a0, a1, a2, a3, b0, b1)                                   \
    asm volatile("mma.sync.aligned.m16n8k16.row.col.f32.f16.f16.f32 "         \
                 "{%0,%1,%2,%3}, {%4,%5,%6,%7}, {%8,%9}, {%0,%1,%2,%3};"      \
                 : "+f"(c[0]), "+f"(c[1]), "+f"(c[2]), "+f"(c[3])             \
                 : "r"(a0), "r"(a1), "r"(a2), "r"(a3), "r"(b0), "r"(b1))

__global__ __launch_bounds__(256) void fused_gemm_kernel(const float* __restrict__ W) {
    __shared__ __half Xs[NUM_T][SSTRIDE];
    __shared__ __half Ws[NT][SSTRIDE];

    int tid  = threadIdx.x;
    int w    = tid >> 5;
    int lane = tid & 31;
    int nbase = blockIdx.x * NT;
    int kbase = blockIdx.y * KPER;
    int mrow  = (w >> 1) * 16;
    int ncol  = (w & 1) * 32;

    float acc[4][4];
    #pragma unroll
    for (int i = 0; i < 4; i++)
        #pragma unroll
        for (int j = 0; j < 4; j++) acc[i][j] = 0.0f;

    int q = lane >> 3, li = lane & 7;
    uint32_t a_base = (uint32_t)__cvta_generic_to_shared(
        &Xs[mrow + (q & 1) * 8 + li][(q >> 1) * 8]);
    uint32_t b_base0 = (uint32_t)__cvta_generic_to_shared(
        &Ws[ncol + (q >> 1) * 8 + li][(q & 1) * 8]);
    uint32_t b_base1 = b_base0 + 16 * SSTRIDE * 2;

    // W load map: 4 threads per row, 16 consecutive floats each (half a 32-block)
    int wrow = tid >> 2;
    int wk   = (tid & 3) << 4;
    const float* wp = W + (size_t)(nbase + wrow) * DIN + kbase + wk;
    // X load map: 2 uint4 per thread
    int c0 = tid, c1 = tid + 256;
    const __half* xp0 = &g_xq[(c0 >> 3) * DIN + kbase + (c0 & 7) * 8];
    const __half* xp1 = &g_xq[(c1 >> 3) * DIN + kbase + (c1 & 7) * 8];

    float4 wv[4];
    uint4  xv[2];
    // prologue load (chunk 0)
    #pragma unroll
    for (int j = 0; j < 4; j++)
        wv[j] = reinterpret_cast<const float4*>(wp)[j];
    xv[0] = *reinterpret_cast<const uint4*>(xp0);
    xv[1] = *reinterpret_cast<const uint4*>(xp1);

    #pragma unroll 1
    for (int c16 = 0; c16 < KPER / KC; c16++) {
        // ---- stage: X copy + W quantize into smem ----
        *reinterpret_cast<uint4*>(&Xs[c0 >> 3][(c0 & 7) * 8]) = xv[0];
        *reinterpret_cast<uint4*>(&Xs[c1 >> 3][(c1 & 7) * 8]) = xv[1];
        {
            float am = 0.0f;
            #pragma unroll
            for (int j = 0; j < 4; j++)
                am = fmaxf(am, fmaxf(fmaxf(fabsf(wv[j].x), fabsf(wv[j].y)),
                                     fmaxf(fabsf(wv[j].z), fabsf(wv[j].w))));
            am = fmaxf(am, __shfl_xor_sync(0xffffffffu, am, 1));  // pair -> 32-block amax
            float scale, inv;
            mk_scale(am, scale, inv);
            uint32_t qq[8];
            #pragma unroll
            for (int j = 0; j < 4; j++) {
                __half2 h0 = __floats2half2_rn(qdq1(wv[j].x, inv, scale),
                                               qdq1(wv[j].y, inv, scale));
                __half2 h1 = __floats2half2_rn(qdq1(wv[j].z, inv, scale),
                                               qdq1(wv[j].w, inv, scale));
                qq[2 * j]     = *reinterpret_cast<uint32_t*>(&h0);
                qq[2 * j + 1] = *reinterpret_cast<uint32_t*>(&h1);
            }
            *reinterpret_cast<uint4*>(&Ws[wrow][wk])     = make_uint4(qq[0], qq[1], qq[2], qq[3]);
            *reinterpret_cast<uint4*>(&Ws[wrow][wk + 8]) = make_uint4(qq[4], qq[5], qq[6], qq[7]);
        }
        __syncthreads();

        // ---- prefetch next chunk while MMA runs ----
        if (c16 + 1 < KPER / KC) {
            int kc = (c16 + 1) * KC;
            #pragma unroll
            for (int j = 0; j < 4; j++)
                wv[j] = reinterpret_cast<const float4*>(wp + kc)[j];
            xv[0] = *reinterpret_cast<const uint4*>(xp0 + kc);
            xv[1] = *reinterpret_cast<const uint4*>(xp1 + kc);
        }

        // ---- MMA over the staged 64x64x64 tile ----
        #pragma unroll
        for (int ks = 0; ks < 4; ks++) {
            uint32_t a0, a1, a2, a3;
            LDMATRIX_X4(a0, a1, a2, a3, a_base + ks * 32);
            #pragma unroll
            for (int nb = 0; nb < 2; nb++) {
                uint32_t b0, b1, b2, b3;
                LDMATRIX_X4(b0, b1, b2, b3, (nb ? b_base1 : b_base0) + ks * 32);
                MMA16816(acc[nb * 2 + 0], a0, a1, a2, a3, b0, b1);
                MMA16816(acc[nb * 2 + 1], a0, a1, a2, a3, b2, b3);
            }
        }
        __syncthreads();
    }

    // epilogue: fp32 partials (no bias here)
    float* pb = g_part + (size_t)blockIdx.y * NUM_T * DOUT;
    int tg = lane >> 2, tig = lane & 3;
    #pragma unroll
    for (int nf = 0; nf < 4; nf++) {
        int col = nbase + ncol + nf * 8 + tig * 2;
        int r0  = mrow + tg;
        pb[(size_t)r0 * DOUT + col]           = acc[nf][0];
        pb[(size_t)r0 * DOUT + col + 1]       = acc[nf][1];
        pb[(size_t)(r0 + 8) * DOUT + col]     = acc[nf][2];
        pb[(size_t)(r0 + 8) * DOUT + col + 1] = acc[nf][3];
    }
}

// ---------------------------------------------------------------------------
// Reduce K-splits + bias qdq (inline). 1 thread = 1 float4 of output.
// 8 consecutive lanes cover one 32-elem bias block (alignment: 2752 % 8 == 0).
// ---------------------------------------------------------------------------
__global__ void reduce_bias_kernel(const float* __restrict__ bias, float* __restrict__ out) {
    int t  = blockIdx.x * blockDim.x + threadIdx.x;    // 0 .. 176127
    int m  = t / (DOUT / 4);
    int o  = (t % (DOUT / 4)) * 4;

    float4 b4 = *reinterpret_cast<const float4*>(bias + o);
    float am = fmaxf(fmaxf(fabsf(b4.x), fabsf(b4.y)), fmaxf(fabsf(b4.z), fabsf(b4.w)));
    am = fmaxf(am, __shfl_xor_sync(0xffffffffu, am, 1));
    am = fmaxf(am, __shfl_xor_sync(0xffffffffu, am, 2));
    am = fmaxf(am, __shfl_xor_sync(0xffffffffu, am, 4));
    float scale, inv;
    mk_scale(am, scale, inv);
    float b0 = qdq1(b4.x, inv, scale);
    float b1 = qdq1(b4.y, inv, scale);
    float b2 = qdq1(b4.z, inv, scale);
    float b3 = qdq1(b4.w, inv, scale);

    size_t idx = (size_t)m * DOUT + o;
    const size_t ps = (size_t)NUM_T * DOUT;
    float4 s0 = *reinterpret_cast<const float4*>(g_part + idx);
    float4 s1 = *reinterpret_cast<const float4*>(g_part + ps + idx);
    float4 s2 = *reinterpret_cast<const float4*>(g_part + 2 * ps + idx);
    float4 s3 = *reinterpret_cast<const float4*>(g_part + 3 * ps + idx);

    float4 r;
    r.x = (s0.x + s1.x) + (s2.x + s3.x) + b0;
    r.y = (s0.y + s1.y) + (s2.y + s3.y) + b1;
    r.z = (s0.z + s1.z) + (s2.z + s3.z) + b2;
    r.w = (s0.w + s1.w) + (s2.w + s3.w) + b3;
    *reinterpret_cast<float4*>(out + idx) = r;
}

// ---------------------------------------------------------------------------
extern "C" void kernel_launch(void* const* d_in, const int* in_sizes, int n_in,
                              void* d_out, int out_size) {
    const float* x = nullptr;
    const float* wgt = nullptr;
    const float* bias = nullptr;
    for (int i = 0; i < n_in; i++) {
        if (in_sizes[i] == NUM_T * DIN)     x    = (const float*)d_in[i];
        else if (in_sizes[i] == DOUT * DIN) wgt  = (const float*)d_in[i];
        else if (in_sizes[i] == DOUT)       bias = (const float*)d_in[i];
    }
    float* out = (float*)d_out;

    qdq_x_kernel<<<(NUM_T * DIN / 128 + 7) / 8, 256>>>(x);
    fused_gemm_kernel<<<dim3(DOUT / NT, KS), 256>>>(wgt);
    reduce_bias_kernel<<<(NUM_T * DOUT / 4) / 256, 256>>>(bias, out);
    (void)out_size;
}

// round 4
// speedup vs baseline: 1.9893x; 1.1183x over previous
#include <cuda_runtime.h>
#include <cuda_fp16.h>
#include <cstdint>

#define NUM_T 64
#define DIN   4096
#define DOUT  11008
#define KS    4
#define KPER  (DIN / KS)     // 1024
#define KC    64
#define NT    64
#define SSTRIDE 72           // +8 half pad: row stride 144B (16B-aligned, conflict-free ldmatrix)

// Scratch (allocation-free rule: __device__ globals)
__device__ __align__(256) __half g_xq[NUM_T * DIN];
__device__ __align__(256) float  g_part[KS * NUM_T * DOUT];   // 11.27 MB

// ---------------------------------------------------------------------------
// MXFP4 block constants from amax (all integer bit-pattern construction):
//   se  = clip(floor(log2 amax) - 2, -127, 127)     (scale = 2^se, never built)
//   c6s = 6 * 2^se      (clip value;  1.5 * 2^(se+2))
//   cM  = 2^(se+22)     (magic: ulp of [M,2M) = 2^(se-1) = half the subnormal step)
//   c2s_bits = bits(2^(se+1))  (threshold: below this use absolute 0.5*scale grid)
// Valid for all se in [-127,127] (all three stay normal fp32).
// ---------------------------------------------------------------------------
__device__ __forceinline__ void mk_consts(float amax, float& c6s, float& cM,
                                          uint32_t& c2s_bits) {
    if (!(amax > 0.0f)) amax = 1.0f;
    int e  = ((__float_as_int(amax) >> 23) & 0xFF) - 127;  // floor(log2) for normals
    int se = min(max(e - 2, -127), 127);
    c6s = __int_as_float(((se + 129) << 23) | 0x400000);   // 1.5 * 2^(se+2)
    cM  = __int_as_float((se + 149) << 23);                // 2^(se+22)
    c2s_bits = (uint32_t)((se + 128) << 23);               // bits of 2^(se+1)
}

// E2M1 quant-dequant in the t-domain (no scale multiplies). Exactly matches
// reference: clip to 6*scale, RNE on grid {step=2^(e-1)*scale, e in [0,2],
// absolute 0.5*scale below 2*scale}. 9 SASS ops, int/float pipe balanced.
__device__ __forceinline__ float qdq_fast(float t, float c6s, float cM,
                                          uint32_t c2s_bits) {
    float a = fminf(fabsf(t), c6s);
    uint32_t u = __float_as_uint(a);
    // RNE to 1 explicit mantissa bit (relative path, exact for a >= 2*scale)
    uint32_t r1 = (u + 0x1FFFFFu + ((u >> 22) & 1u)) & 0xFFC00000u;
    // RNE to multiples of 0.5*scale (magic add; exact, ulp([M,2M)) = scale/2)
    float q2 = __fadd_rn(__fadd_rn(a, cM), -cM);
    uint32_t q = (u < c2s_bits) ? __float_as_uint(q2) : r1;
    return __uint_as_float(q | (__float_as_uint(t) & 0x80000000u));
}

// ---------------------------------------------------------------------------
// x quant-dequant -> f16. One MXFP block (32 floats) = 8 lanes x float4.
// ---------------------------------------------------------------------------
__global__ void qdq_x_kernel(const float* __restrict__ in) {
    int gtid = blockIdx.x * blockDim.x + threadIdx.x;
    int warp = gtid >> 5;
    int lane = threadIdx.x & 31;
    long base = (long)warp * 128 + (long)lane * 4;
    if (base >= NUM_T * DIN) return;
    float4 v = *reinterpret_cast<const float4*>(in + base);
    float am = fmaxf(fmaxf(fabsf(v.x), fabsf(v.y)), fmaxf(fabsf(v.z), fabsf(v.w)));
    am = fmaxf(am, __shfl_xor_sync(0xffffffffu, am, 1));
    am = fmaxf(am, __shfl_xor_sync(0xffffffffu, am, 2));
    am = fmaxf(am, __shfl_xor_sync(0xffffffffu, am, 4));
    float c6s, cM; uint32_t c2sb;
    mk_consts(am, c6s, cM, c2sb);
    __half2 h0 = __floats2half2_rn(qdq_fast(v.x, c6s, cM, c2sb),
                                   qdq_fast(v.y, c6s, cM, c2sb));
    __half2 h1 = __floats2half2_rn(qdq_fast(v.z, c6s, cM, c2sb),
                                   qdq_fast(v.w, c6s, cM, c2sb));
    uint2 st;
    st.x = *reinterpret_cast<uint32_t*>(&h0);
    st.y = *reinterpret_cast<uint32_t*>(&h1);
    *reinterpret_cast<uint2*>(&g_xq[base]) = st;
}

// ---------------------------------------------------------------------------
// Fused GEMM: partial[s] = xq[64,KPER] @ qdq(W[n:n+64, s*KPER:(s+1)*KPER])^T
// CTA 64(M) x 64(N) x KPER(K), 256 thr (8 warps 4x2), W quantized in-register.
// ---------------------------------------------------------------------------
#define LDMATRIX_X4(r0, r1, r2, r3, addr)                                        \
    asm volatile("ldmatrix.sync.aligned.m8n8.x4.shared.b16 {%0,%1,%2,%3}, [%4];" \
                 : "=r"(r0), "=r"(r1), "=r"(r2), "=r"(r3) : "r"(addr))

#define MMA16816(c, a0, a1, a2, a3, b0, b1)                                   \
    asm volatile("mma.sync.aligned.m16n8k16.row.col.f32.f16.f16.f32 "         \
                 "{%0,%1,%2,%3}, {%4,%5,%6,%7}, {%8,%9}, {%0,%1,%2,%3};"      \
                 : "+f"(c[0]), "+f"(c[1]), "+f"(c[2]), "+f"(c[3])             \
                 : "r"(a0), "r"(a1), "r"(a2), "r"(a3), "r"(b0), "r"(b1))

__global__ __launch_bounds__(256) void fused_gemm_kernel(const float* __restrict__ W) {
    __shared__ __half Xs[NUM_T][SSTRIDE];
    __shared__ __half Ws[NT][SSTRIDE];

    int tid  = threadIdx.x;
    int w    = tid >> 5;
    int lane = tid & 31;
    int nbase = blockIdx.x * NT;
    int kbase = blockIdx.y * KPER;
    int mrow  = (w >> 1) * 16;
    int ncol  = (w & 1) * 32;

    float acc[4][4];
    #pragma unroll
    for (int i = 0; i < 4; i++)
        #pragma unroll
        for (int j = 0; j < 4; j++) acc[i][j] = 0.0f;

    int q = lane >> 3, li = lane & 7;
    uint32_t a_base = (uint32_t)__cvta_generic_to_shared(
        &Xs[mrow + (q & 1) * 8 + li][(q >> 1) * 8]);
    uint32_t b_base0 = (uint32_t)__cvta_generic_to_shared(
        &Ws[ncol + (q >> 1) * 8 + li][(q & 1) * 8]);
    uint32_t b_base1 = b_base0 + 16 * SSTRIDE * 2;

    // W load map: 4 threads per row, 16 consecutive floats each (half a 32-block)
    int wrow = tid >> 2;
    int wk   = (tid & 3) << 4;
    const float* wp = W + (size_t)(nbase + wrow) * DIN + kbase + wk;
    // X load map: 2 uint4 per thread
    int c0 = tid, c1 = tid + 256;
    const __half* xp0 = &g_xq[(c0 >> 3) * DIN + kbase + (c0 & 7) * 8];
    const __half* xp1 = &g_xq[(c1 >> 3) * DIN + kbase + (c1 & 7) * 8];

    float4 wv[4];
    uint4  xv[2];
    // prologue load (chunk 0)
    #pragma unroll
    for (int j = 0; j < 4; j++)
        wv[j] = reinterpret_cast<const float4*>(wp)[j];
    xv[0] = *reinterpret_cast<const uint4*>(xp0);
    xv[1] = *reinterpret_cast<const uint4*>(xp1);

    #pragma unroll 1
    for (int c16 = 0; c16 < KPER / KC; c16++) {
        // ---- stage: X copy + W quantize into smem ----
        *reinterpret_cast<uint4*>(&Xs[c0 >> 3][(c0 & 7) * 8]) = xv[0];
        *reinterpret_cast<uint4*>(&Xs[c1 >> 3][(c1 & 7) * 8]) = xv[1];
        {
            float am = 0.0f;
            #pragma unroll
            for (int j = 0; j < 4; j++)
                am = fmaxf(am, fmaxf(fmaxf(fabsf(wv[j].x), fabsf(wv[j].y)),
                                     fmaxf(fabsf(wv[j].z), fabsf(wv[j].w))));
            am = fmaxf(am, __shfl_xor_sync(0xffffffffu, am, 1));  // pair -> 32-block amax
            float c6s, cM; uint32_t c2sb;
            mk_consts(am, c6s, cM, c2sb);
            uint32_t qq[8];
            #pragma unroll
            for (int j = 0; j < 4; j++) {
                __half2 h0 = __floats2half2_rn(qdq_fast(wv[j].x, c6s, cM, c2sb),
                                               qdq_fast(wv[j].y, c6s, cM, c2sb));
                __half2 h1 = __floats2half2_rn(qdq_fast(wv[j].z, c6s, cM, c2sb),
                                               qdq_fast(wv[j].w, c6s, cM, c2sb));
                qq[2 * j]     = *reinterpret_cast<uint32_t*>(&h0);
                qq[2 * j + 1] = *reinterpret_cast<uint32_t*>(&h1);
            }
            *reinterpret_cast<uint4*>(&Ws[wrow][wk])     = make_uint4(qq[0], qq[1], qq[2], qq[3]);
            *reinterpret_cast<uint4*>(&Ws[wrow][wk + 8]) = make_uint4(qq[4], qq[5], qq[6], qq[7]);
        }
        __syncthreads();

        // ---- prefetch next chunk while MMA runs ----
        if (c16 + 1 < KPER / KC) {
            int kc = (c16 + 1) * KC;
            #pragma unroll
            for (int j = 0; j < 4; j++)
                wv[j] = reinterpret_cast<const float4*>(wp + kc)[j];
            xv[0] = *reinterpret_cast<const uint4*>(xp0 + kc);
            xv[1] = *reinterpret_cast<const uint4*>(xp1 + kc);
        }

        // ---- MMA over the staged 64x64x64 tile ----
        #pragma unroll
        for (int ks = 0; ks < 4; ks++) {
            uint32_t a0, a1, a2, a3;
            LDMATRIX_X4(a0, a1, a2, a3, a_base + ks * 32);
            #pragma unroll
            for (int nb = 0; nb < 2; nb++) {
                uint32_t b0, b1, b2, b3;
                LDMATRIX_X4(b0, b1, b2, b3, (nb ? b_base1 : b_base0) + ks * 32);
                MMA16816(acc[nb * 2 + 0], a0, a1, a2, a3, b0, b1);
                MMA16816(acc[nb * 2 + 1], a0, a1, a2, a3, b2, b3);
            }
        }
        __syncthreads();
    }

    // epilogue: fp32 partials (no bias here)
    float* pb = g_part + (size_t)blockIdx.y * NUM_T * DOUT;
    int tg = lane >> 2, tig = lane & 3;
    #pragma unroll
    for (int nf = 0; nf < 4; nf++) {
        int col = nbase + ncol + nf * 8 + tig * 2;
        int r0  = mrow + tg;
        pb[(size_t)r0 * DOUT + col]           = acc[nf][0];
        pb[(size_t)r0 * DOUT + col + 1]       = acc[nf][1];
        pb[(size_t)(r0 + 8) * DOUT + col]     = acc[nf][2];
        pb[(size_t)(r0 + 8) * DOUT + col + 1] = acc[nf][3];
    }
}

// ---------------------------------------------------------------------------
// Reduce K-splits + bias qdq (inline). 1 thread = 1 float4 of output.
// 8 consecutive lanes cover one 32-elem bias block (alignment: 2752 % 8 == 0).
// ---------------------------------------------------------------------------
__global__ void reduce_bias_kernel(const float* __restrict__ bias, float* __restrict__ out) {
    int t  = blockIdx.x * blockDim.x + threadIdx.x;    // 0 .. 176127
    int m  = t / (DOUT / 4);
    int o  = (t % (DOUT / 4)) * 4;

    float4 b4 = *reinterpret_cast<const float4*>(bias + o);
    float am = fmaxf(fmaxf(fabsf(b4.x), fabsf(b4.y)), fmaxf(fabsf(b4.z), fabsf(b4.w)));
    am = fmaxf(am, __shfl_xor_sync(0xffffffffu, am, 1));
    am = fmaxf(am, __shfl_xor_sync(0xffffffffu, am, 2));
    am = fmaxf(am, __shfl_xor_sync(0xffffffffu, am, 4));
    float c6s, cM; uint32_t c2sb;
    mk_consts(am, c6s, cM, c2sb);
    float b0 = qdq_fast(b4.x, c6s, cM, c2sb);
    float b1 = qdq_fast(b4.y, c6s, cM, c2sb);
    float b2 = qdq_fast(b4.z, c6s, cM, c2sb);
    float b3 = qdq_fast(b4.w, c6s, cM, c2sb);

    size_t idx = (size_t)m * DOUT + o;
    const size_t ps = (size_t)NUM_T * DOUT;
    float4 s0 = *reinterpret_cast<const float4*>(g_part + idx);
    float4 s1 = *reinterpret_cast<const float4*>(g_part + ps + idx);
    float4 s2 = *reinterpret_cast<const float4*>(g_part + 2 * ps + idx);
    float4 s3 = *reinterpret_cast<const float4*>(g_part + 3 * ps + idx);

    float4 r;
    r.x = (s0.x + s1.x) + (s2.x + s3.x) + b0;
    r.y = (s0.y + s1.y) + (s2.y + s3.y) + b1;
    r.z = (s0.z + s1.z) + (s2.z + s3.z) + b2;
    r.w = (s0.w + s1.w) + (s2.w + s3.w) + b3;
    *reinterpret_cast<float4*>(out + idx) = r;
}

// ---------------------------------------------------------------------------
extern "C" void kernel_launch(void* const* d_in, const int* in_sizes, int n_in,
                              void* d_out, int out_size) {
    const float* x = nullptr;
    const float* wgt = nullptr;
    const float* bias = nullptr;
    for (int i = 0; i < n_in; i++) {
        if (in_sizes[i] == NUM_T * DIN)     x    = (const float*)d_in[i];
        else if (in_sizes[i] == DOUT * DIN) wgt  = (const float*)d_in[i];
        else if (in_sizes[i] == DOUT)       bias = (const float*)d_in[i];
    }
    float* out = (float*)d_out;

    qdq_x_kernel<<<NUM_T * DIN / 4 / 128, 128>>>(x);
    fused_gemm_kernel<<<dim3(DOUT / NT, KS), 256>>>(wgt);
    reduce_bias_kernel<<<(NUM_T * DOUT / 4) / 256, 256>>>(bias, out);
    (void)out_size;
}

// round 5
// speedup vs baseline: 2.1122x; 1.0618x over previous
#include <cuda_runtime.h>
#include <cuda_fp16.h>
#include <cstdint>

#define NUM_T 64
#define DIN   4096
#define DOUT  11008
#define KS    4
#define KPER  (DIN / KS)     // 1024
#define KC    64
#define NCHUNK (KPER / KC)   // 16
#define NT    64
#define SSTRIDE 72           // +8 half pad: row stride 144B (16B-aligned, conflict-free ldmatrix)
#define STAGE_BYTES (NUM_T * SSTRIDE * 2)   // 9216

// Scratch (allocation-free rule: __device__ globals)
__device__ __align__(256) __half g_xq[NUM_T * DIN];
__device__ __align__(256) float  g_part[KS * NUM_T * DOUT];   // 11.27 MB

// ---------------------------------------------------------------------------
// MXFP4 block constants from amax (integer bit-pattern construction):
//   se  = clip(floor(log2 amax) - 2, -127, 127)     (scale = 2^se, never built)
//   c6s = 6 * 2^se ; cM = 2^(se+22) (magic) ; c2s_bits = bits(2^(se+1))
// ---------------------------------------------------------------------------
__device__ __forceinline__ void mk_consts(float amax, float& c6s, float& cM,
                                          uint32_t& c2s_bits) {
    if (!(amax > 0.0f)) amax = 1.0f;
    int e  = ((__float_as_int(amax) >> 23) & 0xFF) - 127;
    int se = min(max(e - 2, -127), 127);
    c6s = __int_as_float(((se + 129) << 23) | 0x400000);   // 1.5 * 2^(se+2)
    cM  = __int_as_float((se + 149) << 23);                // 2^(se+22)
    c2s_bits = (uint32_t)((se + 128) << 23);               // bits of 2^(se+1)
}

// E2M1 qdq in the t-domain (no per-element scale mults). Matches reference
// exactly: clip to 6*scale, RNE on E2M1 grid incl. 0.5*scale subnormal step.
__device__ __forceinline__ float qdq_fast(float t, float c6s, float cM,
                                          uint32_t c2s_bits) {
    float a = fminf(fabsf(t), c6s);
    uint32_t u = __float_as_uint(a);
    uint32_t r1 = (u + 0x1FFFFFu + ((u >> 22) & 1u)) & 0xFFC00000u;  // RNE, 1 mant bit
    float q2 = __fadd_rn(__fadd_rn(a, cM), -cM);                     // RNE to scale/2 grid
    uint32_t q = (u < c2s_bits) ? __float_as_uint(q2) : r1;
    return __uint_as_float(q | (__float_as_uint(t) & 0x80000000u));
}

// ---------------------------------------------------------------------------
// x quant-dequant -> f16. One MXFP block (32 floats) = 8 lanes x float4.
// ---------------------------------------------------------------------------
__global__ void qdq_x_kernel(const float* __restrict__ in) {
    int gtid = blockIdx.x * blockDim.x + threadIdx.x;
    int warp = gtid >> 5;
    int lane = threadIdx.x & 31;
    long base = (long)warp * 128 + (long)lane * 4;
    if (base >= NUM_T * DIN) return;
    float4 v = *reinterpret_cast<const float4*>(in + base);
    float am = fmaxf(fmaxf(fabsf(v.x), fabsf(v.y)), fmaxf(fabsf(v.z), fabsf(v.w)));
    am = fmaxf(am, __shfl_xor_sync(0xffffffffu, am, 1));
    am = fmaxf(am, __shfl_xor_sync(0xffffffffu, am, 2));
    am = fmaxf(am, __shfl_xor_sync(0xffffffffu, am, 4));
    float c6s, cM; uint32_t c2sb;
    mk_consts(am, c6s, cM, c2sb);
    __half2 h0 = __floats2half2_rn(qdq_fast(v.x, c6s, cM, c2sb),
                                   qdq_fast(v.y, c6s, cM, c2sb));
    __half2 h1 = __floats2half2_rn(qdq_fast(v.z, c6s, cM, c2sb),
                                   qdq_fast(v.w, c6s, cM, c2sb));
    uint2 st;
    st.x = *reinterpret_cast<uint32_t*>(&h0);
    st.y = *reinterpret_cast<uint32_t*>(&h1);
    *reinterpret_cast<uint2*>(&g_xq[base]) = st;
}

// ---------------------------------------------------------------------------
// Fused GEMM, double-buffered: quant(chunk c+1) overlaps MMA(chunk c).
// One __syncthreads per chunk.
// ---------------------------------------------------------------------------
#define LDMATRIX_X4(r0, r1, r2, r3, addr)                                        \
    asm volatile("ldmatrix.sync.aligned.m8n8.x4.shared.b16 {%0,%1,%2,%3}, [%4];" \
                 : "=r"(r0), "=r"(r1), "=r"(r2), "=r"(r3) : "r"(addr))

#define MMA16816(c, a0, a1, a2, a3, b0, b1)                                   \
    asm volatile("mma.sync.aligned.m16n8k16.row.col.f32.f16.f16.f32 "         \
                 "{%0,%1,%2,%3}, {%4,%5,%6,%7}, {%8,%9}, {%0,%1,%2,%3};"      \
                 : "+f"(c[0]), "+f"(c[1]), "+f"(c[2]), "+f"(c[3])             \
                 : "r"(a0), "r"(a1), "r"(a2), "r"(a3), "r"(b0), "r"(b1))

__global__ __launch_bounds__(256) void fused_gemm_kernel(const float* __restrict__ W) {
    __shared__ __half Xs[2][NUM_T][SSTRIDE];
    __shared__ __half Ws[2][NT][SSTRIDE];

    int tid  = threadIdx.x;
    int w    = tid >> 5;
    int lane = tid & 31;
    int nbase = blockIdx.x * NT;
    int kbase = blockIdx.y * KPER;
    int mrow  = (w >> 1) * 16;
    int ncol  = (w & 1) * 32;

    float acc[4][4];
    #pragma unroll
    for (int i = 0; i < 4; i++)
        #pragma unroll
        for (int j = 0; j < 4; j++) acc[i][j] = 0.0f;

    int q = lane >> 3, li = lane & 7;
    uint32_t a_base0 = (uint32_t)__cvta_generic_to_shared(
        &Xs[0][mrow + (q & 1) * 8 + li][(q >> 1) * 8]);
    uint32_t b_base0 = (uint32_t)__cvta_generic_to_shared(
        &Ws[0][ncol + (q >> 1) * 8 + li][(q & 1) * 8]);

    // W load map: 4 threads per row, 16 consecutive floats each (half a 32-block)
    int wrow = tid >> 2;
    int wk   = (tid & 3) << 4;
    const float* wp = W + (size_t)(nbase + wrow) * DIN + kbase + wk;
    // X load map: 2 uint4 per thread
    int c0 = tid, c1 = tid + 256;
    int xr0 = c0 >> 3, xc0 = (c0 & 7) * 8;
    int xr1 = c1 >> 3, xc1 = (c1 & 7) * 8;
    const __half* xp0 = &g_xq[xr0 * DIN + kbase + xc0];
    const __half* xp1 = &g_xq[xr1 * DIN + kbase + xc1];

    float4 wv[4];
    uint4  xv[2];

    // -------- prologue: load chunk0, quant -> stage0, load chunk1 --------
    #pragma unroll
    for (int j = 0; j < 4; j++)
        wv[j] = reinterpret_cast<const float4*>(wp)[j];
    xv[0] = *reinterpret_cast<const uint4*>(xp0);
    xv[1] = *reinterpret_cast<const uint4*>(xp1);
    {
        *reinterpret_cast<uint4*>(&Xs[0][xr0][xc0]) = xv[0];
        *reinterpret_cast<uint4*>(&Xs[0][xr1][xc1]) = xv[1];
        float am = 0.0f;
        #pragma unroll
        for (int j = 0; j < 4; j++)
            am = fmaxf(am, fmaxf(fmaxf(fabsf(wv[j].x), fabsf(wv[j].y)),
                                 fmaxf(fabsf(wv[j].z), fabsf(wv[j].w))));
        am = fmaxf(am, __shfl_xor_sync(0xffffffffu, am, 1));
        float c6s, cM; uint32_t c2sb;
        mk_consts(am, c6s, cM, c2sb);
        uint32_t qq[8];
        #pragma unroll
        for (int j = 0; j < 4; j++) {
            __half2 h0 = __floats2half2_rn(qdq_fast(wv[j].x, c6s, cM, c2sb),
                                           qdq_fast(wv[j].y, c6s, cM, c2sb));
            __half2 h1 = __floats2half2_rn(qdq_fast(wv[j].z, c6s, cM, c2sb),
                                           qdq_fast(wv[j].w, c6s, cM, c2sb));
            qq[2 * j]     = *reinterpret_cast<uint32_t*>(&h0);
            qq[2 * j + 1] = *reinterpret_cast<uint32_t*>(&h1);
        }
        *reinterpret_cast<uint4*>(&Ws[0][wrow][wk])     = make_uint4(qq[0], qq[1], qq[2], qq[3]);
        *reinterpret_cast<uint4*>(&Ws[0][wrow][wk + 8]) = make_uint4(qq[4], qq[5], qq[6], qq[7]);
    }
    #pragma unroll
    for (int j = 0; j < 4; j++)
        wv[j] = reinterpret_cast<const float4*>(wp + KC)[j];
    xv[0] = *reinterpret_cast<const uint4*>(xp0 + KC);
    xv[1] = *reinterpret_cast<const uint4*>(xp1 + KC);
    __syncthreads();

    // -------- main loop: one barrier per chunk --------
    #pragma unroll 1
    for (int c16 = 0; c16 < NCHUNK; c16++) {
        int nxt = (c16 + 1) & 1;
        // quant chunk c16+1 (in regs) into the other stage
        if (c16 + 1 < NCHUNK) {
            *reinterpret_cast<uint4*>(&Xs[nxt][xr0][xc0]) = xv[0];
            *reinterpret_cast<uint4*>(&Xs[nxt][xr1][xc1]) = xv[1];
            float am = 0.0f;
            #pragma unroll
            for (int j = 0; j < 4; j++)
                am = fmaxf(am, fmaxf(fmaxf(fabsf(wv[j].x), fabsf(wv[j].y)),
                                     fmaxf(fabsf(wv[j].z), fabsf(wv[j].w))));
            am = fmaxf(am, __shfl_xor_sync(0xffffffffu, am, 1));
            float c6s, cM; uint32_t c2sb;
            mk_consts(am, c6s, cM, c2sb);
            uint32_t qq[8];
            #pragma unroll
            for (int j = 0; j < 4; j++) {
                __half2 h0 = __floats2half2_rn(qdq_fast(wv[j].x, c6s, cM, c2sb),
                                               qdq_fast(wv[j].y, c6s, cM, c2sb));
                __half2 h1 = __floats2half2_rn(qdq_fast(wv[j].z, c6s, cM, c2sb),
                                               qdq_fast(wv[j].w, c6s, cM, c2sb));
                qq[2 * j]     = *reinterpret_cast<uint32_t*>(&h0);
                qq[2 * j + 1] = *reinterpret_cast<uint32_t*>(&h1);
            }
            *reinterpret_cast<uint4*>(&Ws[nxt][wrow][wk])     = make_uint4(qq[0], qq[1], qq[2], qq[3]);
            *reinterpret_cast<uint4*>(&Ws[nxt][wrow][wk + 8]) = make_uint4(qq[4], qq[5], qq[6], qq[7]);
        }
        // prefetch chunk c16+2 into regs
        if (c16 + 2 < NCHUNK) {
            int kc = (c16 + 2) * KC;
            #pragma unroll
            for (int j = 0; j < 4; j++)
                wv[j] = reinterpret_cast<const float4*>(wp + kc)[j];
            xv[0] = *reinterpret_cast<const uint4*>(xp0 + kc);
            xv[1] = *reinterpret_cast<const uint4*>(xp1 + kc);
        }
        // MMA over staged chunk c16
        uint32_t a_s = a_base0 + (c16 & 1) * STAGE_BYTES;
        uint32_t b_s = b_base0 + (c16 & 1) * STAGE_BYTES;
        #pragma unroll
        for (int ks = 0; ks < 4; ks++) {
            uint32_t a0, a1, a2, a3;
            LDMATRIX_X4(a0, a1, a2, a3, a_s + ks * 32);
            #pragma unroll
            for (int nb = 0; nb < 2; nb++) {
                uint32_t b0, b1, b2, b3;
                LDMATRIX_X4(b0, b1, b2, b3, b_s + nb * 16 * SSTRIDE * 2 + ks * 32);
                MMA16816(acc[nb * 2 + 0], a0, a1, a2, a3, b0, b1);
                MMA16816(acc[nb * 2 + 1], a0, a1, a2, a3, b2, b3);
            }
        }
        __syncthreads();
    }

    // epilogue: fp32 partials
    float* pb = g_part + (size_t)blockIdx.y * NUM_T * DOUT;
    int tg = lane >> 2, tig = lane & 3;
    #pragma unroll
    for (int nf = 0; nf < 4; nf++) {
        int col = nbase + ncol + nf * 8 + tig * 2;
        int r0  = mrow + tg;
        pb[(size_t)r0 * DOUT + col]           = acc[nf][0];
        pb[(size_t)r0 * DOUT + col + 1]       = acc[nf][1];
        pb[(size_t)(r0 + 8) * DOUT + col]     = acc[nf][2];
        pb[(size_t)(r0 + 8) * DOUT + col + 1] = acc[nf][3];
    }
}

// ---------------------------------------------------------------------------
// Reduce K-splits + bias qdq (inline). 1 thread = 1 float4 of output.
// ---------------------------------------------------------------------------
__global__ void reduce_bias_kernel(const float* __restrict__ bias, float* __restrict__ out) {
    int t  = blockIdx.x * blockDim.x + threadIdx.x;
    int m  = t / (DOUT / 4);
    int o  = (t % (DOUT / 4)) * 4;

    float4 b4 = *reinterpret_cast<const float4*>(bias + o);
    float am = fmaxf(fmaxf(fabsf(b4.x), fabsf(b4.y)), fmaxf(fabsf(b4.z), fabsf(b4.w)));
    am = fmaxf(am, __shfl_xor_sync(0xffffffffu, am, 1));
    am = fmaxf(am, __shfl_xor_sync(0xffffffffu, am, 2));
    am = fmaxf(am, __shfl_xor_sync(0xffffffffu, am, 4));
    float c6s, cM; uint32_t c2sb;
    mk_consts(am, c6s, cM, c2sb);
    float b0 = qdq_fast(b4.x, c6s, cM, c2sb);
    float b1 = qdq_fast(b4.y, c6s, cM, c2sb);
    float b2 = qdq_fast(b4.z, c6s, cM, c2sb);
    float b3 = qdq_fast(b4.w, c6s, cM, c2sb);

    size_t idx = (size_t)m * DOUT + o;
    const size_t ps = (size_t)NUM_T * DOUT;
    float4 s0 = *reinterpret_cast<const float4*>(g_part + idx);
    float4 s1 = *reinterpret_cast<const float4*>(g_part + ps + idx);
    float4 s2 = *reinterpret_cast<const float4*>(g_part + 2 * ps + idx);
    float4 s3 = *reinterpret_cast<const float4*>(g_part + 3 * ps + idx);

    float4 r;
    r.x = (s0.x + s1.x) + (s2.x + s3.x) + b0;
    r.y = (s0.y + s1.y) + (s2.y + s3.y) + b1;
    r.z = (s0.z + s1.z) + (s2.z + s3.z) + b2;
    r.w = (s0.w + s1.w) + (s2.w + s3.w) + b3;
    *reinterpret_cast<float4*>(out + idx) = r;
}

// ---------------------------------------------------------------------------
extern "C" void kernel_launch(void* const* d_in, const int* in_sizes, int n_in,
                              void* d_out, int out_size) {
    const float* x = nullptr;
    const float* wgt = nullptr;
    const float* bias = nullptr;
    for (int i = 0; i < n_in; i++) {
        if (in_sizes[i] == NUM_T * DIN)     x    = (const float*)d_in[i];
        else if (in_sizes[i] == DOUT * DIN) wgt  = (const float*)d_in[i];
        else if (in_sizes[i] == DOUT)       bias = (const float*)d_in[i];
    }
    float* out = (float*)d_out;

    qdq_x_kernel<<<NUM_T * DIN / 4 / 128, 128>>>(x);
    fused_gemm_kernel<<<dim3(DOUT / NT, KS), 256>>>(wgt);
    reduce_bias_kernel<<<(NUM_T * DOUT / 4) / 256, 256>>>(bias, out);
    (void)out_size;
}